// round 1
// baseline (speedup 1.0000x reference)
#include <cuda_runtime.h>
#include <math.h>

// Problem dims
// B=4, T=4096 -> M=16384 rows; H=2048; D=256; NH=4; K=32; NB=65536; NG=16; NK=NH*K=128

// ---------------- device scratch (no allocations allowed) ----------------
__device__ float g_partial[64 * 2048];
__device__ float g_meanq[2048];
__device__ float g_q1024[1024];
__device__ float g_rq[256];
__device__ float g_scores[65536];
__device__ float g_candV[8192];
__device__ int   g_candI[8192];
__device__ int   g_topk[32];
__device__ float g_keys[32 * 256];
__device__ float g_vals[32 * 256];
__device__ float g_bias[32];
__device__ float g_temp[4];
__device__ float g_W1[2048 * 128];   // [h][nk], temp/sqrt(D) folded in
__device__ float g_W2[128 * 2048];   // [nk][j]
__device__ float g_attn[16384 * 128];

// ---------------- 1) column sums of hidden (mean over B*T) ----------------
// grid (64 row-chunks, 8 col-chunks), block 256
__global__ void k_colsum(const float* __restrict__ hidden) {
    int col = blockIdx.y * 256 + threadIdx.x;
    int r0  = blockIdx.x * 256;
    const float* p = hidden + (size_t)r0 * 2048 + col;
    float s = 0.f;
#pragma unroll 8
    for (int r = 0; r < 256; r++) s += p[(size_t)r * 2048];
    g_partial[blockIdx.x * 2048 + col] = s;
}

// grid 8, block 256
__global__ void k_mean() {
    int col = blockIdx.x * 256 + threadIdx.x;
    float s = 0.f;
#pragma unroll
    for (int r = 0; r < 64; r++) s += g_partial[r * 2048 + col];
    g_meanq[col] = s * (1.0f / 16384.0f);
}

// ---------------- 2) q1024 = Wq @ mean_query ----------------
// grid 128, block 256 (8 warps, one row per warp)
__global__ void k_q1024(const float* __restrict__ Wq) {
    int row  = (blockIdx.x << 3) + (threadIdx.x >> 5);
    int lane = threadIdx.x & 31;
    const float* wp = Wq + (size_t)row * 2048;
    float s = 0.f;
#pragma unroll 8
    for (int j = 0; j < 64; j++) s += wp[j * 32 + lane] * g_meanq[j * 32 + lane];
#pragma unroll
    for (int off = 16; off > 0; off >>= 1) s += __shfl_xor_sync(0xffffffffu, s, off);
    if (lane == 0) g_q1024[row] = s;
}

// rough_query = mean over 4 heads. 1 block, 256 threads
__global__ void k_rq() {
    int d = threadIdx.x;
    g_rq[d] = 0.25f * (g_q1024[d] + g_q1024[256 + d] + g_q1024[512 + d] + g_q1024[768 + d]);
}

// ---------------- 3) rough scores ----------------
// grid 8192, block 256 (one belief per warp)
__global__ void k_rough(const float* __restrict__ beliefs, const int* __restrict__ mask) {
    int w    = (blockIdx.x << 3) + (threadIdx.x >> 5);
    int lane = threadIdx.x & 31;
    const float* bp = beliefs + (size_t)w * 256;
    float dot = 0.f, ss = 0.f;
#pragma unroll
    for (int j = 0; j < 8; j++) {
        float v = bp[j * 32 + lane];
        dot += v * g_rq[j * 32 + lane];
        ss  += v * v;
    }
#pragma unroll
    for (int off = 16; off > 0; off >>= 1) {
        dot += __shfl_xor_sync(0xffffffffu, dot, off);
        ss  += __shfl_xor_sync(0xffffffffu, ss, off);
    }
    if (lane == 0) {
        float score = dot / fmaxf(sqrtf(ss), 1e-8f);
        g_scores[w] = (mask[w] != 0) ? score : -1e30f;
    }
}

// ---------------- 4) top-32 selection (order-free, set only matters) ----------------
// Stage A: per-chunk (256 elems) top-32. grid 256, block 256
__global__ void k_topA() {
    __shared__ float sv[256];
    __shared__ float rv[256];
    __shared__ int   ri[256];
    int t = threadIdx.x;
    sv[t] = g_scores[blockIdx.x * 256 + t];
    __syncthreads();
    for (int it = 0; it < 32; it++) {
        rv[t] = sv[t]; ri[t] = t;
        __syncthreads();
        for (int s = 128; s > 0; s >>= 1) {
            if (t < s && rv[t + s] > rv[t]) { rv[t] = rv[t + s]; ri[t] = ri[t + s]; }
            __syncthreads();
        }
        if (t == 0) {
            int li = ri[0];
            g_candV[blockIdx.x * 32 + it] = rv[0];
            g_candI[blockIdx.x * 32 + it] = blockIdx.x * 256 + li;
            sv[li] = -INFINITY;
        }
        __syncthreads();
    }
}

// Stage B: global top-32 over 8192 candidates. 1 block, 1024 threads
__global__ void k_topB() {
    __shared__ float sv[1024];
    __shared__ int   si[1024];
    int t = threadIdx.x;
    for (int it = 0; it < 32; it++) {
        float bv = -INFINITY; int bi = 0;
#pragma unroll
        for (int j = 0; j < 8; j++) {
            int idx = t + j * 1024;
            float v = g_candV[idx];
            if (v > bv) { bv = v; bi = idx; }
        }
        sv[t] = bv; si[t] = bi;
        __syncthreads();
        for (int s = 512; s > 0; s >>= 1) {
            if (t < s && sv[t + s] > sv[t]) { sv[t] = sv[t + s]; si[t] = si[t + s]; }
            __syncthreads();
        }
        if (t == 0) {
            int ci = si[0];
            g_topk[it] = g_candI[ci];
            g_candV[ci] = -INFINITY;
        }
        __syncthreads();
    }
}

// ---------------- 5) keys / values / goal bias / temperature ----------------
// 1 block, 1024 threads (32 warps; warp w owns key w)
__global__ void k_prep(const float* __restrict__ beliefs,
                       const float* __restrict__ ge,
                       const float* __restrict__ gp,
                       const float* __restrict__ lt) {
    __shared__ float gA[16][256];
    __shared__ float gpS[16];
    int t = threadIdx.x, w = t >> 5, lane = t & 31;
    if (t < 4)  g_temp[t] = fmaxf(expf(lt[t]), 0.1f);
    if (t < 16) gpS[t] = gp[t];

    int idx = g_topk[w];
    float v[8], kreg[8];
    float ss = 0.f;
#pragma unroll
    for (int j = 0; j < 8; j++) {
        v[j] = beliefs[(size_t)idx * 256 + j * 32 + lane];
        ss += v[j] * v[j];
    }
#pragma unroll
    for (int off = 16; off > 0; off >>= 1) ss += __shfl_xor_sync(0xffffffffu, ss, off);
    float inv = 1.0f / fmaxf(sqrtf(ss), 1e-8f);
#pragma unroll
    for (int j = 0; j < 8; j++) {
        kreg[j] = v[j] * inv;
        g_keys[w * 256 + j * 32 + lane] = kreg[j];
        g_vals[w * 256 + j * 32 + lane] = v[j];
    }
    // normalize goals into smem (warps 0..15)
    if (w < 16) {
        float gv[8]; float gs = 0.f;
#pragma unroll
        for (int j = 0; j < 8; j++) {
            gv[j] = ge[w * 256 + j * 32 + lane];
            gs += gv[j] * gv[j];
        }
#pragma unroll
        for (int off = 16; off > 0; off >>= 1) gs += __shfl_xor_sync(0xffffffffu, gs, off);
        float gi = 1.0f / fmaxf(sqrtf(gs), 1e-8f);
#pragma unroll
        for (int j = 0; j < 8; j++) gA[w][j * 32 + lane] = gv[j] * gi;
    }
    __syncthreads();
    // bias[w] = max_g (keys[w] . gA[g]) * prio[g]
    float best = -INFINITY;
#pragma unroll
    for (int g = 0; g < 16; g++) {
        float d = 0.f;
#pragma unroll
        for (int j = 0; j < 8; j++) d += kreg[j] * gA[g][j * 32 + lane];
#pragma unroll
        for (int off = 16; off > 0; off >>= 1) d += __shfl_xor_sync(0xffffffffu, d, off);
        best = fmaxf(best, d * gpS[g]);
    }
    if (lane == 0) g_bias[w] = best;
}

// ---------------- 6) W1[h][nk] = temp[n]/16 * sum_d Wq[n*256+d][h]*keys[k][d] ----------------
// grid (32 h-tiles of 64, 4 heads), block 256
__global__ void __launch_bounds__(256) k_W1(const float* __restrict__ Wq) {
    __shared__ float keysS[32 * 256];
    __shared__ float aS[8 * 64];
    int t = threadIdx.x;
    int h0 = blockIdx.x * 64;
    int head = blockIdx.y;
#pragma unroll
    for (int i = 0; i < 32; i++) keysS[t + i * 256] = g_keys[t + i * 256];
    float acc[8];
#pragma unroll
    for (int j = 0; j < 8; j++) acc[j] = 0.f;
    int k4 = t >> 6, hl = t & 63;
    for (int dc = 0; dc < 32; dc++) {
        __syncthreads();
#pragma unroll
        for (int i = 0; i < 2; i++) {
            int e = t + i * 256;
            int dd = e >> 6, hh = e & 63;
            aS[dd * 64 + hh] = Wq[(size_t)(head * 256 + dc * 8 + dd) * 2048 + h0 + hh];
        }
        __syncthreads();
#pragma unroll
        for (int dd = 0; dd < 8; dd++) {
            float a = aS[dd * 64 + hl];
            int dg = dc * 8 + dd;
#pragma unroll
            for (int j = 0; j < 8; j++) acc[j] += a * keysS[(k4 * 8 + j) * 256 + dg];
        }
    }
    float scale = g_temp[head] * 0.0625f;  // temp / sqrt(256)
#pragma unroll
    for (int j = 0; j < 8; j++)
        g_W1[(h0 + hl) * 128 + head * 32 + k4 * 8 + j] = acc[j] * scale;
}

// ---------------- 7) W2[nk][j] = sum_d values[k][d]*Wo[j][n*256+d] ----------------
// grid 2048 (one j per block), block 128 (one nk per thread)
__global__ void __launch_bounds__(128) k_W2(const float* __restrict__ Wo) {
    __shared__ float woS[1024];
    __shared__ float valT[256 * 32];
    int t = threadIdx.x;
    int j = blockIdx.x;
#pragma unroll
    for (int i = 0; i < 8; i++) woS[t + i * 128] = Wo[(size_t)j * 1024 + t + i * 128];
#pragma unroll
    for (int i = 0; i < 64; i++) {
        int e = t + i * 128;
        int k = e >> 8, d = e & 255;
        valT[d * 32 + k] = g_vals[e];
    }
    __syncthreads();
    int n = t >> 5, k = t & 31;
    float acc = 0.f;
#pragma unroll 8
    for (int d = 0; d < 256; d++) acc += valT[d * 32 + k] * woS[n * 256 + d];
    g_W2[t * 2048 + j] = acc;
}

// ---------------- 8) GEMM1 fused with bias + softmax: attn = softmax(hidden@W1 + bias) ----------------
// grid 256 (64-row tiles), block 256. Output tile 64x128.
__global__ void __launch_bounds__(256) k_gemm1(const float* __restrict__ hidden) {
    __shared__ __align__(16) float hS[32 * 65];    // [kk][row], padded
    __shared__ __align__(16) float w1S[32 * 128];  // [kk][col]
    int t = threadIdx.x;
    int tx = t & 31, ty = t >> 5;
    int m0 = blockIdx.x * 64;
    float4 acc[8];
#pragma unroll
    for (int i = 0; i < 8; i++) acc[i] = make_float4(0.f, 0.f, 0.f, 0.f);

    for (int hc = 0; hc < 64; hc++) {
        int h0 = hc * 32;
#pragma unroll
        for (int i = 0; i < 8; i++) {
            int e = t + i * 256;
            int kk = e & 31, r = e >> 5;
            hS[kk * 65 + r] = hidden[(size_t)(m0 + r) * 2048 + h0 + kk];
        }
#pragma unroll
        for (int i = 0; i < 16; i++) {
            int e = t + i * 256;
            int c = e & 127, kk = e >> 7;
            w1S[kk * 128 + c] = g_W1[(h0 + kk) * 128 + c];
        }
        __syncthreads();
#pragma unroll
        for (int kk = 0; kk < 32; kk++) {
            float4 b = *reinterpret_cast<const float4*>(&w1S[kk * 128 + tx * 4]);
#pragma unroll
            for (int i = 0; i < 8; i++) {
                float a = hS[kk * 65 + ty * 8 + i];
                acc[i].x += a * b.x; acc[i].y += a * b.y;
                acc[i].z += a * b.z; acc[i].w += a * b.w;
            }
        }
        __syncthreads();
    }
    // epilogue: bias + per-(row,head) softmax over 32 cols (8 lanes x 4 cols)
    float b0 = g_bias[(tx * 4 + 0) & 31];
    float b1 = g_bias[(tx * 4 + 1) & 31];
    float b2 = g_bias[(tx * 4 + 2) & 31];
    float b3 = g_bias[(tx * 4 + 3) & 31];
#pragma unroll
    for (int i = 0; i < 8; i++) {
        float s0 = acc[i].x + b0, s1 = acc[i].y + b1;
        float s2 = acc[i].z + b2, s3 = acc[i].w + b3;
        float mx = fmaxf(fmaxf(s0, s1), fmaxf(s2, s3));
#pragma unroll
        for (int off = 1; off < 8; off <<= 1) mx = fmaxf(mx, __shfl_xor_sync(0xffffffffu, mx, off));
        float e0 = expf(s0 - mx), e1 = expf(s1 - mx);
        float e2 = expf(s2 - mx), e3 = expf(s3 - mx);
        float sm = e0 + e1 + e2 + e3;
#pragma unroll
        for (int off = 1; off < 8; off <<= 1) sm += __shfl_xor_sync(0xffffffffu, sm, off);
        float inv = 1.0f / sm;
        float4 o = make_float4(e0 * inv, e1 * inv, e2 * inv, e3 * inv);
        *reinterpret_cast<float4*>(&g_attn[(size_t)(m0 + ty * 8 + i) * 128 + tx * 4]) = o;
    }
}

// ---------------- 9) GEMM2: out = attn @ W2 ----------------
// grid (16 col-tiles, 256 row-tiles), block 256. Output tile 64x128, full reduction 128.
__global__ void __launch_bounds__(256) k_gemm2(float* __restrict__ out) {
    __shared__ __align__(16) float aS[64 * 128];
    __shared__ __align__(16) float w2S[32 * 128];
    int t = threadIdx.x;
    int tx = t & 31, ty = t >> 5;
    int c0 = blockIdx.x * 128;
    int m0 = blockIdx.y * 64;
#pragma unroll
    for (int i = 0; i < 32; i++) aS[t + i * 256] = g_attn[(size_t)m0 * 128 + t + i * 256];
    float4 acc[8];
#pragma unroll
    for (int i = 0; i < 8; i++) acc[i] = make_float4(0.f, 0.f, 0.f, 0.f);
    for (int rc = 0; rc < 4; rc++) {
#pragma unroll
        for (int i = 0; i < 16; i++) {
            int e = t + i * 256;
            int c = e & 127, kk = e >> 7;
            w2S[kk * 128 + c] = g_W2[(rc * 32 + kk) * 2048 + c0 + c];
        }
        __syncthreads();
#pragma unroll
        for (int kk = 0; kk < 32; kk++) {
            float4 b = *reinterpret_cast<const float4*>(&w2S[kk * 128 + tx * 4]);
#pragma unroll
            for (int i = 0; i < 8; i++) {
                float a = aS[(ty * 8 + i) * 128 + rc * 32 + kk];
                acc[i].x += a * b.x; acc[i].y += a * b.y;
                acc[i].z += a * b.z; acc[i].w += a * b.w;
            }
        }
        __syncthreads();
    }
#pragma unroll
    for (int i = 0; i < 8; i++) {
        *reinterpret_cast<float4*>(&out[(size_t)(m0 + ty * 8 + i) * 2048 + c0 + tx * 4]) = acc[i];
    }
}

// ---------------- launch ----------------
extern "C" void kernel_launch(void* const* d_in, const int* in_sizes, int n_in,
                              void* d_out, int out_size) {
    const float* hidden   = (const float*)d_in[0];
    const float* beliefs  = (const float*)d_in[1];
    const int*   mask     = (const int*)d_in[2];
    const float* goal_emb = (const float*)d_in[3];
    const float* goal_pri = (const float*)d_in[4];
    const float* Wq       = (const float*)d_in[5];
    const float* Wo       = (const float*)d_in[6];
    const float* log_temp = (const float*)d_in[7];
    float* out = (float*)d_out;

    k_colsum<<<dim3(64, 8), 256>>>(hidden);
    k_mean<<<8, 256>>>();
    k_q1024<<<128, 256>>>(Wq);
    k_rq<<<1, 256>>>();
    k_rough<<<8192, 256>>>(beliefs, mask);
    k_topA<<<256, 256>>>();
    k_topB<<<1, 1024>>>();
    k_prep<<<1, 1024>>>(beliefs, goal_emb, goal_pri, log_temp);
    k_W1<<<dim3(32, 4), 256>>>(Wq);
    k_W2<<<2048, 128>>>(Wo);
    k_gemm1<<<256, 256>>>(hidden);
    k_gemm2<<<dim3(16, 256), 256>>>(out);
}

// round 2
// speedup vs baseline: 1.1278x; 1.1278x over previous
#include <cuda_runtime.h>
#include <math.h>

// Problem dims
// B=4, T=4096 -> M=16384 rows; H=2048; D=256; NH=4; K=32; NB=65536; NG=16; NK=NH*K=128

// ---------------- device scratch (no allocations allowed) ----------------
__device__ float g_partial[64 * 2048];
__device__ float g_meanq[2048];
__device__ float g_q1024[1024];
__device__ float g_rq[256];
__device__ float g_scores[65536];
__device__ float g_candV[8192];
__device__ int   g_candI[8192];
__device__ int   g_topk[32];
__device__ float g_keys[32 * 256];
__device__ float g_vals[32 * 256];
__device__ float g_bias[32];
__device__ float g_temp[4];
__device__ float g_W1[2048 * 128];   // [h][nk], temp/sqrt(D) folded in
__device__ float g_W2[128 * 2048];   // [nk][j]
__device__ float g_attn[16384 * 128];

// ---------------- f32x2 helpers ----------------
__device__ __forceinline__ void fma2(unsigned long long& d, unsigned long long a, unsigned long long b) {
    asm("fma.rn.f32x2 %0, %1, %2, %0;" : "+l"(d) : "l"(a), "l"(b));
}
__device__ __forceinline__ unsigned long long pack2(float x) {
    unsigned long long r;
    asm("mov.b64 %0, {%1, %1};" : "=l"(r) : "f"(x));
    return r;
}
__device__ __forceinline__ float lo32(unsigned long long v) { return __uint_as_float((unsigned)v); }
__device__ __forceinline__ float hi32(unsigned long long v) { return __uint_as_float((unsigned)(v >> 32)); }

// ---------------- 1) column sums of hidden (mean over B*T) ----------------
__global__ void k_colsum(const float* __restrict__ hidden) {
    int col = blockIdx.y * 256 + threadIdx.x;
    int r0  = blockIdx.x * 256;
    const float* p = hidden + (size_t)r0 * 2048 + col;
    float s = 0.f;
#pragma unroll 8
    for (int r = 0; r < 256; r++) s += p[(size_t)r * 2048];
    g_partial[blockIdx.x * 2048 + col] = s;
}

__global__ void k_mean() {
    int col = blockIdx.x * 256 + threadIdx.x;
    float s = 0.f;
#pragma unroll
    for (int r = 0; r < 64; r++) s += g_partial[r * 2048 + col];
    g_meanq[col] = s * (1.0f / 16384.0f);
}

// ---------------- 2) q1024 = Wq @ mean_query ----------------
__global__ void k_q1024(const float* __restrict__ Wq) {
    int row  = (blockIdx.x << 3) + (threadIdx.x >> 5);
    int lane = threadIdx.x & 31;
    const float* wp = Wq + (size_t)row * 2048;
    float s = 0.f;
#pragma unroll 8
    for (int j = 0; j < 64; j++) s += wp[j * 32 + lane] * g_meanq[j * 32 + lane];
#pragma unroll
    for (int off = 16; off > 0; off >>= 1) s += __shfl_xor_sync(0xffffffffu, s, off);
    if (lane == 0) g_q1024[row] = s;
}

__global__ void k_rq() {
    int d = threadIdx.x;
    g_rq[d] = 0.25f * (g_q1024[d] + g_q1024[256 + d] + g_q1024[512 + d] + g_q1024[768 + d]);
}

// ---------------- 3) rough scores ----------------
__global__ void k_rough(const float* __restrict__ beliefs, const int* __restrict__ mask) {
    int w    = (blockIdx.x << 3) + (threadIdx.x >> 5);
    int lane = threadIdx.x & 31;
    const float* bp = beliefs + (size_t)w * 256;
    float dot = 0.f, ss = 0.f;
#pragma unroll
    for (int j = 0; j < 8; j++) {
        float v = bp[j * 32 + lane];
        dot += v * g_rq[j * 32 + lane];
        ss  += v * v;
    }
#pragma unroll
    for (int off = 16; off > 0; off >>= 1) {
        dot += __shfl_xor_sync(0xffffffffu, dot, off);
        ss  += __shfl_xor_sync(0xffffffffu, ss, off);
    }
    if (lane == 0) {
        float score = dot / fmaxf(sqrtf(ss), 1e-8f);
        g_scores[w] = (mask[w] != 0) ? score : -1e30f;
    }
}

// ---------------- 4) top-32 (order-free; softmax is permutation-invariant in k) ----------------
__global__ void k_topA() {
    __shared__ float sv[256];
    __shared__ float rv[256];
    __shared__ int   ri[256];
    int t = threadIdx.x;
    sv[t] = g_scores[blockIdx.x * 256 + t];
    __syncthreads();
    for (int it = 0; it < 32; it++) {
        rv[t] = sv[t]; ri[t] = t;
        __syncthreads();
        for (int s = 128; s > 0; s >>= 1) {
            if (t < s && rv[t + s] > rv[t]) { rv[t] = rv[t + s]; ri[t] = ri[t + s]; }
            __syncthreads();
        }
        if (t == 0) {
            int li = ri[0];
            g_candV[blockIdx.x * 32 + it] = rv[0];
            g_candI[blockIdx.x * 32 + it] = blockIdx.x * 256 + li;
            sv[li] = -INFINITY;
        }
        __syncthreads();
    }
}

__global__ void k_topB() {
    __shared__ float sv[1024];
    __shared__ int   si[1024];
    int t = threadIdx.x;
    for (int it = 0; it < 32; it++) {
        float bv = -INFINITY; int bi = 0;
#pragma unroll
        for (int j = 0; j < 8; j++) {
            int idx = t + j * 1024;
            float v = g_candV[idx];
            if (v > bv) { bv = v; bi = idx; }
        }
        sv[t] = bv; si[t] = bi;
        __syncthreads();
        for (int s = 512; s > 0; s >>= 1) {
            if (t < s && sv[t + s] > sv[t]) { sv[t] = sv[t + s]; si[t] = si[t + s]; }
            __syncthreads();
        }
        if (t == 0) {
            int ci = si[0];
            g_topk[it] = g_candI[ci];
            g_candV[ci] = -INFINITY;
        }
        __syncthreads();
    }
}

// ---------------- 5) keys / values / goal bias / temperature ----------------
__global__ void k_prep(const float* __restrict__ beliefs,
                       const float* __restrict__ ge,
                       const float* __restrict__ gp,
                       const float* __restrict__ lt) {
    __shared__ float gA[16][256];
    __shared__ float gpS[16];
    int t = threadIdx.x, w = t >> 5, lane = t & 31;
    if (t < 4)  g_temp[t] = fmaxf(expf(lt[t]), 0.1f);
    if (t < 16) gpS[t] = gp[t];

    int idx = g_topk[w];
    float v[8], kreg[8];
    float ss = 0.f;
#pragma unroll
    for (int j = 0; j < 8; j++) {
        v[j] = beliefs[(size_t)idx * 256 + j * 32 + lane];
        ss += v[j] * v[j];
    }
#pragma unroll
    for (int off = 16; off > 0; off >>= 1) ss += __shfl_xor_sync(0xffffffffu, ss, off);
    float inv = 1.0f / fmaxf(sqrtf(ss), 1e-8f);
#pragma unroll
    for (int j = 0; j < 8; j++) {
        kreg[j] = v[j] * inv;
        g_keys[w * 256 + j * 32 + lane] = kreg[j];
        g_vals[w * 256 + j * 32 + lane] = v[j];
    }
    if (w < 16) {
        float gv[8]; float gs = 0.f;
#pragma unroll
        for (int j = 0; j < 8; j++) {
            gv[j] = ge[w * 256 + j * 32 + lane];
            gs += gv[j] * gv[j];
        }
#pragma unroll
        for (int off = 16; off > 0; off >>= 1) gs += __shfl_xor_sync(0xffffffffu, gs, off);
        float gi = 1.0f / fmaxf(sqrtf(gs), 1e-8f);
#pragma unroll
        for (int j = 0; j < 8; j++) gA[w][j * 32 + lane] = gv[j] * gi;
    }
    __syncthreads();
    float best = -INFINITY;
#pragma unroll
    for (int g = 0; g < 16; g++) {
        float d = 0.f;
#pragma unroll
        for (int j = 0; j < 8; j++) d += kreg[j] * gA[g][j * 32 + lane];
#pragma unroll
        for (int off = 16; off > 0; off >>= 1) d += __shfl_xor_sync(0xffffffffu, d, off);
        best = fmaxf(best, d * gpS[g]);
    }
    if (lane == 0) g_bias[w] = best;
}

// ---------------- 6) W1[h][nk] = temp[n]/16 * sum_d Wq[n*256+d][h]*keys[k][d] ----------------
__global__ void __launch_bounds__(256) k_W1(const float* __restrict__ Wq) {
    __shared__ float keysS[32 * 256];
    __shared__ float aS[8 * 64];
    int t = threadIdx.x;
    int h0 = blockIdx.x * 64;
    int head = blockIdx.y;
#pragma unroll
    for (int i = 0; i < 32; i++) keysS[t + i * 256] = g_keys[t + i * 256];
    float acc[8];
#pragma unroll
    for (int j = 0; j < 8; j++) acc[j] = 0.f;
    int k4 = t >> 6, hl = t & 63;
    for (int dc = 0; dc < 32; dc++) {
        __syncthreads();
#pragma unroll
        for (int i = 0; i < 2; i++) {
            int e = t + i * 256;
            int dd = e >> 6, hh = e & 63;
            aS[dd * 64 + hh] = Wq[(size_t)(head * 256 + dc * 8 + dd) * 2048 + h0 + hh];
        }
        __syncthreads();
#pragma unroll
        for (int dd = 0; dd < 8; dd++) {
            float a = aS[dd * 64 + hl];
            int dg = dc * 8 + dd;
#pragma unroll
            for (int j = 0; j < 8; j++) acc[j] += a * keysS[(k4 * 8 + j) * 256 + dg];
        }
    }
    float scale = g_temp[head] * 0.0625f;
#pragma unroll
    for (int j = 0; j < 8; j++)
        g_W1[(h0 + hl) * 128 + head * 32 + k4 * 8 + j] = acc[j] * scale;
}

// ---------------- 7) W2[nk][j] = sum_d values[k][d]*Wo[j][n*256+d] ----------------
__global__ void __launch_bounds__(128) k_W2(const float* __restrict__ Wo) {
    __shared__ float woS[1024];
    __shared__ float valT[256 * 32];
    int t = threadIdx.x;
    int j = blockIdx.x;
#pragma unroll
    for (int i = 0; i < 8; i++) woS[t + i * 128] = Wo[(size_t)j * 1024 + t + i * 128];
#pragma unroll
    for (int i = 0; i < 64; i++) {
        int e = t + i * 128;
        int k = e >> 8, d = e & 255;
        valT[d * 32 + k] = g_vals[e];
    }
    __syncthreads();
    int n = t >> 5, k = t & 31;
    float acc = 0.f;
#pragma unroll 8
    for (int d = 0; d < 256; d++) acc += valT[d * 32 + k] * woS[n * 256 + d];
    g_W2[t * 2048 + j] = acc;
}

// ---------------- 8) GEMM1 + bias + softmax: attn = softmax(hidden @ W1 + bias) ----------------
// grid 256 (64-row tiles), block 128. Thread tile 8 rows x 8 cols. f32x2 FMA.
__global__ void __launch_bounds__(128) k_gemm1(const float* __restrict__ hidden) {
    __shared__ __align__(16) float hS[32 * 66];    // [kk][row], pad 66 (even)
    __shared__ __align__(16) float w1S[32 * 128];  // [kk][col]
    int t = threadIdx.x;
    int tx = t & 15, ty = t >> 4;          // tx: 8-col group, ty: 8-row group
    int m0 = blockIdx.x * 64;

    unsigned long long acc[8][4];          // [col][rowpair]
#pragma unroll
    for (int c = 0; c < 8; c++)
#pragma unroll
        for (int rp = 0; rp < 4; rp++) acc[c][rp] = 0ull;

    for (int hc = 0; hc < 64; hc++) {
        int h0 = hc * 32;
#pragma unroll
        for (int i = 0; i < 16; i++) {
            int e = t + i * 128;
            int kk = e & 31, r = e >> 5;
            hS[kk * 66 + r] = hidden[(size_t)(m0 + r) * 2048 + h0 + kk];
        }
#pragma unroll
        for (int i = 0; i < 32; i++) {
            int e = t + i * 128;
            int c = e & 127, kk = e >> 7;
            w1S[kk * 128 + c] = g_W1[(h0 + kk) * 128 + c];
        }
        __syncthreads();
#pragma unroll 8
        for (int kk = 0; kk < 32; kk++) {
            const float* hrow = &hS[kk * 66 + ty * 8];
            unsigned long long a0 = *(const unsigned long long*)(hrow + 0);
            unsigned long long a1 = *(const unsigned long long*)(hrow + 2);
            unsigned long long a2 = *(const unsigned long long*)(hrow + 4);
            unsigned long long a3 = *(const unsigned long long*)(hrow + 6);
            float4 b0 = *(const float4*)&w1S[kk * 128 + tx * 8];
            float4 b1 = *(const float4*)&w1S[kk * 128 + tx * 8 + 4];
            unsigned long long bb[8];
            bb[0] = pack2(b0.x); bb[1] = pack2(b0.y); bb[2] = pack2(b0.z); bb[3] = pack2(b0.w);
            bb[4] = pack2(b1.x); bb[5] = pack2(b1.y); bb[6] = pack2(b1.z); bb[7] = pack2(b1.w);
#pragma unroll
            for (int c = 0; c < 8; c++) {
                fma2(acc[c][0], a0, bb[c]);
                fma2(acc[c][1], a1, bb[c]);
                fma2(acc[c][2], a2, bb[c]);
                fma2(acc[c][3], a3, bb[c]);
            }
        }
        __syncthreads();
    }

    // epilogue: bias + per-(row,head) softmax over 32 cols; head group = 4 lanes x 8 cols
    float bias[8];
#pragma unroll
    for (int c = 0; c < 8; c++) bias[c] = g_bias[(tx * 8 + c) & 31];

#pragma unroll
    for (int rp = 0; rp < 4; rp++) {
#pragma unroll
        for (int half = 0; half < 2; half++) {
            int r = rp * 2 + half;
            float s[8];
#pragma unroll
            for (int c = 0; c < 8; c++)
                s[c] = (half ? hi32(acc[c][rp]) : lo32(acc[c][rp])) + bias[c];
            float mx = s[0];
#pragma unroll
            for (int c = 1; c < 8; c++) mx = fmaxf(mx, s[c]);
            mx = fmaxf(mx, __shfl_xor_sync(0xffffffffu, mx, 1));
            mx = fmaxf(mx, __shfl_xor_sync(0xffffffffu, mx, 2));
            float e[8], sm = 0.f;
#pragma unroll
            for (int c = 0; c < 8; c++) { e[c] = __expf(s[c] - mx); sm += e[c]; }
            sm += __shfl_xor_sync(0xffffffffu, sm, 1);
            sm += __shfl_xor_sync(0xffffffffu, sm, 2);
            float inv = 1.0f / sm;
            float* dst = &g_attn[(size_t)(m0 + ty * 8 + r) * 128 + tx * 8];
            *reinterpret_cast<float4*>(dst)     = make_float4(e[0]*inv, e[1]*inv, e[2]*inv, e[3]*inv);
            *reinterpret_cast<float4*>(dst + 4) = make_float4(e[4]*inv, e[5]*inv, e[6]*inv, e[7]*inv);
        }
    }
}

// ---------------- 9) GEMM2: out = attn @ W2 ----------------
// grid (16 col-tiles, 256 row-tiles), block 128. Thread tile 8x8. f32x2 FMA.
__global__ void __launch_bounds__(128) k_gemm2(float* __restrict__ out) {
    __shared__ __align__(16) float aT[128 * 66];   // [k][row], pad 66
    __shared__ __align__(16) float w2S[32 * 128];  // [kk][col]
    int t = threadIdx.x;
    int tx = t & 15, ty = t >> 4;
    int c0 = blockIdx.x * 128;
    int m0 = blockIdx.y * 64;

    // load + transpose attn tile: aT[k][row]
#pragma unroll 16
    for (int i = 0; i < 64; i++)
        aT[t * 66 + i] = g_attn[(size_t)(m0 + i) * 128 + t];

    unsigned long long acc[8][4];
#pragma unroll
    for (int c = 0; c < 8; c++)
#pragma unroll
        for (int rp = 0; rp < 4; rp++) acc[c][rp] = 0ull;

    for (int rc = 0; rc < 4; rc++) {
#pragma unroll
        for (int i = 0; i < 32; i++)
            w2S[i * 128 + t] = g_W2[(size_t)(rc * 32 + i) * 2048 + c0 + t];
        __syncthreads();
#pragma unroll 8
        for (int kk = 0; kk < 32; kk++) {
            int kg = rc * 32 + kk;
            const float* arow = &aT[kg * 66 + ty * 8];
            unsigned long long a0 = *(const unsigned long long*)(arow + 0);
            unsigned long long a1 = *(const unsigned long long*)(arow + 2);
            unsigned long long a2 = *(const unsigned long long*)(arow + 4);
            unsigned long long a3 = *(const unsigned long long*)(arow + 6);
            float4 b0 = *(const float4*)&w2S[kk * 128 + tx * 8];
            float4 b1 = *(const float4*)&w2S[kk * 128 + tx * 8 + 4];
            unsigned long long bb[8];
            bb[0] = pack2(b0.x); bb[1] = pack2(b0.y); bb[2] = pack2(b0.z); bb[3] = pack2(b0.w);
            bb[4] = pack2(b1.x); bb[5] = pack2(b1.y); bb[6] = pack2(b1.z); bb[7] = pack2(b1.w);
#pragma unroll
            for (int c = 0; c < 8; c++) {
                fma2(acc[c][0], a0, bb[c]);
                fma2(acc[c][1], a1, bb[c]);
                fma2(acc[c][2], a2, bb[c]);
                fma2(acc[c][3], a3, bb[c]);
            }
        }
        __syncthreads();
    }

#pragma unroll
    for (int rp = 0; rp < 4; rp++) {
#pragma unroll
        for (int half = 0; half < 2; half++) {
            int r = rp * 2 + half;
            float* dst = &out[(size_t)(m0 + ty * 8 + r) * 2048 + c0 + tx * 8];
            if (half == 0) {
                *reinterpret_cast<float4*>(dst) =
                    make_float4(lo32(acc[0][rp]), lo32(acc[1][rp]), lo32(acc[2][rp]), lo32(acc[3][rp]));
                *reinterpret_cast<float4*>(dst + 4) =
                    make_float4(lo32(acc[4][rp]), lo32(acc[5][rp]), lo32(acc[6][rp]), lo32(acc[7][rp]));
            } else {
                *reinterpret_cast<float4*>(dst) =
                    make_float4(hi32(acc[0][rp]), hi32(acc[1][rp]), hi32(acc[2][rp]), hi32(acc[3][rp]));
                *reinterpret_cast<float4*>(dst + 4) =
                    make_float4(hi32(acc[4][rp]), hi32(acc[5][rp]), hi32(acc[6][rp]), hi32(acc[7][rp]));
            }
        }
    }
}

// ---------------- launch ----------------
extern "C" void kernel_launch(void* const* d_in, const int* in_sizes, int n_in,
                              void* d_out, int out_size) {
    const float* hidden   = (const float*)d_in[0];
    const float* beliefs  = (const float*)d_in[1];
    const int*   mask     = (const int*)d_in[2];
    const float* goal_emb = (const float*)d_in[3];
    const float* goal_pri = (const float*)d_in[4];
    const float* Wq       = (const float*)d_in[5];
    const float* Wo       = (const float*)d_in[6];
    const float* log_temp = (const float*)d_in[7];
    float* out = (float*)d_out;

    k_colsum<<<dim3(64, 8), 256>>>(hidden);
    k_mean<<<8, 256>>>();
    k_q1024<<<128, 256>>>(Wq);
    k_rq<<<1, 256>>>();
    k_rough<<<8192, 256>>>(beliefs, mask);
    k_topA<<<256, 256>>>();
    k_topB<<<1, 1024>>>();
    k_prep<<<1, 1024>>>(beliefs, goal_emb, goal_pri, log_temp);
    k_W1<<<dim3(32, 4), 256>>>(Wq);
    k_W2<<<2048, 128>>>(Wo);
    k_gemm1<<<256, 128>>>(hidden);
    k_gemm2<<<dim3(16, 256), 128>>>(out);
}

// round 4
// speedup vs baseline: 1.6020x; 1.4205x over previous
#include <cuda_runtime.h>
#include <cuda_bf16.h>
#include <math.h>

// Problem dims
// B=4, T=4096 -> M=16384 rows; H=2048; D=256; NH=4; K=32; NB=65536; NG=16; NK=NH*K=128

// ---------------- device scratch (no allocations allowed) ----------------
__device__ float g_partial[64 * 2048];
__device__ float g_meanq[2048];
__device__ float g_q1024[1024];
__device__ float g_rq[256];
__device__ float g_scores[65536];
__device__ float g_candV[8192];
__device__ int   g_candI[8192];
__device__ int   g_topk[32];
__device__ float g_keys[32 * 256];
__device__ float g_vals[32 * 256];
__device__ float g_bias[32];
__device__ float g_temp[4];

// bf16 hi/lo split planes
__device__ __nv_bfloat16 g_hid_hi[16384 * 2048];
__device__ __nv_bfloat16 g_hid_lo[16384 * 2048];
__device__ __nv_bfloat16 g_W1Thi[128 * 2048];   // [nk][h]
__device__ __nv_bfloat16 g_W1Tlo[128 * 2048];
__device__ __nv_bfloat16 g_W2Thi[2048 * 128];   // [j][nk]
__device__ __nv_bfloat16 g_W2Tlo[2048 * 128];
__device__ __nv_bfloat16 g_attn_hi[16384 * 128];
__device__ __nv_bfloat16 g_attn_lo[16384 * 128];

// ---------------- PTX helpers ----------------
__device__ __forceinline__ unsigned smem_u32(const void* p) {
    return (unsigned)__cvta_generic_to_shared(p);
}
__device__ __forceinline__ void cp16(unsigned dst, const void* src) {
    asm volatile("cp.async.cg.shared.global [%0], [%1], 16;" :: "r"(dst), "l"(src));
}
__device__ __forceinline__ void cp_commit() { asm volatile("cp.async.commit_group;"); }
__device__ __forceinline__ void ldsm4(unsigned* r, unsigned addr) {
    asm volatile("ldmatrix.sync.aligned.m8n8.x4.shared.b16 {%0,%1,%2,%3}, [%4];"
        : "=r"(r[0]), "=r"(r[1]), "=r"(r[2]), "=r"(r[3]) : "r"(addr));
}
// b0 = k[0:8] half, b1 = k[8:16] half of the SAME n8 subtile (non-contiguous regs)
__device__ __forceinline__ void mma16816(float* c, const unsigned* a, unsigned b0, unsigned b1) {
    asm volatile("mma.sync.aligned.m16n8k16.row.col.f32.bf16.bf16.f32 "
        "{%0,%1,%2,%3}, {%4,%5,%6,%7}, {%8,%9}, {%0,%1,%2,%3};"
        : "+f"(c[0]), "+f"(c[1]), "+f"(c[2]), "+f"(c[3])
        : "r"(a[0]), "r"(a[1]), "r"(a[2]), "r"(a[3]), "r"(b0), "r"(b1));
}
__device__ __forceinline__ void split_bf16(float x, __nv_bfloat16& h, __nv_bfloat16& l) {
    h = __float2bfloat16(x);
    l = __float2bfloat16(x - __bfloat162float(h));
}

// ---------------- 1) column sums + hi/lo split of hidden ----------------
__global__ void k_convsum(const float* __restrict__ hidden) {
    int col = blockIdx.y * 256 + threadIdx.x;
    int r0  = blockIdx.x * 256;
    float s = 0.f;
#pragma unroll 4
    for (int r = 0; r < 256; r++) {
        size_t idx = (size_t)(r0 + r) * 2048 + col;
        float x = hidden[idx];
        s += x;
        __nv_bfloat16 h, l;
        split_bf16(x, h, l);
        g_hid_hi[idx] = h;
        g_hid_lo[idx] = l;
    }
    g_partial[blockIdx.x * 2048 + col] = s;
}

__global__ void k_mean() {
    int col = blockIdx.x * 256 + threadIdx.x;
    float s = 0.f;
#pragma unroll
    for (int r = 0; r < 64; r++) s += g_partial[r * 2048 + col];
    g_meanq[col] = s * (1.0f / 16384.0f);
}

// ---------------- 2) q1024 = Wq @ mean_query ----------------
__global__ void k_q1024(const float* __restrict__ Wq) {
    int row  = (blockIdx.x << 3) + (threadIdx.x >> 5);
    int lane = threadIdx.x & 31;
    const float* wp = Wq + (size_t)row * 2048;
    float s = 0.f;
#pragma unroll 8
    for (int j = 0; j < 64; j++) s += wp[j * 32 + lane] * g_meanq[j * 32 + lane];
#pragma unroll
    for (int off = 16; off > 0; off >>= 1) s += __shfl_xor_sync(0xffffffffu, s, off);
    if (lane == 0) g_q1024[row] = s;
}

__global__ void k_rq() {
    int d = threadIdx.x;
    g_rq[d] = 0.25f * (g_q1024[d] + g_q1024[256 + d] + g_q1024[512 + d] + g_q1024[768 + d]);
}

// ---------------- 3) rough scores ----------------
__global__ void k_rough(const float* __restrict__ beliefs, const int* __restrict__ mask) {
    int w    = (blockIdx.x << 3) + (threadIdx.x >> 5);
    int lane = threadIdx.x & 31;
    const float* bp = beliefs + (size_t)w * 256;
    float dot = 0.f, ss = 0.f;
#pragma unroll
    for (int j = 0; j < 8; j++) {
        float v = bp[j * 32 + lane];
        dot += v * g_rq[j * 32 + lane];
        ss  += v * v;
    }
#pragma unroll
    for (int off = 16; off > 0; off >>= 1) {
        dot += __shfl_xor_sync(0xffffffffu, dot, off);
        ss  += __shfl_xor_sync(0xffffffffu, ss, off);
    }
    if (lane == 0) {
        float score = dot / fmaxf(sqrtf(ss), 1e-8f);
        g_scores[w] = (mask[w] != 0) ? score : -1e30f;
    }
}

// ---------------- 4) top-32 (order-free; softmax is permutation-invariant in k) ----------------
__global__ void k_topA() {
    __shared__ float sv[256];
    __shared__ float rv[256];
    __shared__ int   ri[256];
    int t = threadIdx.x;
    sv[t] = g_scores[blockIdx.x * 256 + t];
    __syncthreads();
    for (int it = 0; it < 32; it++) {
        rv[t] = sv[t]; ri[t] = t;
        __syncthreads();
        for (int s = 128; s > 0; s >>= 1) {
            if (t < s && rv[t + s] > rv[t]) { rv[t] = rv[t + s]; ri[t] = ri[t + s]; }
            __syncthreads();
        }
        if (t == 0) {
            int li = ri[0];
            g_candV[blockIdx.x * 32 + it] = rv[0];
            g_candI[blockIdx.x * 32 + it] = blockIdx.x * 256 + li;
            sv[li] = -INFINITY;
        }
        __syncthreads();
    }
}

__global__ void k_topB() {
    __shared__ float sv[1024];
    __shared__ int   si[1024];
    int t = threadIdx.x;
    for (int it = 0; it < 32; it++) {
        float bv = -INFINITY; int bi = 0;
#pragma unroll
        for (int j = 0; j < 8; j++) {
            int idx = t + j * 1024;
            float v = g_candV[idx];
            if (v > bv) { bv = v; bi = idx; }
        }
        sv[t] = bv; si[t] = bi;
        __syncthreads();
        for (int s = 512; s > 0; s >>= 1) {
            if (t < s && sv[t + s] > sv[t]) { sv[t] = sv[t + s]; si[t] = si[t + s]; }
            __syncthreads();
        }
        if (t == 0) {
            int ci = si[0];
            g_topk[it] = g_candI[ci];
            g_candV[ci] = -INFINITY;
        }
        __syncthreads();
    }
}

// ---------------- 5) keys / values / goal bias / temperature ----------------
__global__ void k_prep(const float* __restrict__ beliefs,
                       const float* __restrict__ ge,
                       const float* __restrict__ gp,
                       const float* __restrict__ lt) {
    __shared__ float gA[16][256];
    __shared__ float gpS[16];
    int t = threadIdx.x, w = t >> 5, lane = t & 31;
    if (t < 4)  g_temp[t] = fmaxf(expf(lt[t]), 0.1f);
    if (t < 16) gpS[t] = gp[t];

    int idx = g_topk[w];
    float v[8], kreg[8];
    float ss = 0.f;
#pragma unroll
    for (int j = 0; j < 8; j++) {
        v[j] = beliefs[(size_t)idx * 256 + j * 32 + lane];
        ss += v[j] * v[j];
    }
#pragma unroll
    for (int off = 16; off > 0; off >>= 1) ss += __shfl_xor_sync(0xffffffffu, ss, off);
    float inv = 1.0f / fmaxf(sqrtf(ss), 1e-8f);
#pragma unroll
    for (int j = 0; j < 8; j++) {
        kreg[j] = v[j] * inv;
        g_keys[w * 256 + j * 32 + lane] = kreg[j];
        g_vals[w * 256 + j * 32 + lane] = v[j];
    }
    if (w < 16) {
        float gv[8]; float gs = 0.f;
#pragma unroll
        for (int j = 0; j < 8; j++) {
            gv[j] = ge[w * 256 + j * 32 + lane];
            gs += gv[j] * gv[j];
        }
#pragma unroll
        for (int off = 16; off > 0; off >>= 1) gs += __shfl_xor_sync(0xffffffffu, gs, off);
        float gi = 1.0f / fmaxf(sqrtf(gs), 1e-8f);
#pragma unroll
        for (int j = 0; j < 8; j++) gA[w][j * 32 + lane] = gv[j] * gi;
    }
    __syncthreads();
    float best = -INFINITY;
#pragma unroll
    for (int g = 0; g < 16; g++) {
        float d = 0.f;
#pragma unroll
        for (int j = 0; j < 8; j++) d += kreg[j] * gA[g][j * 32 + lane];
#pragma unroll
        for (int off = 16; off > 0; off >>= 1) d += __shfl_xor_sync(0xffffffffu, d, off);
        best = fmaxf(best, d * gpS[g]);
    }
    if (lane == 0) g_bias[w] = best;
}

// ---------------- 6) W1T[nk][h] = temp/16 * sum_d Wq[head*256+d][h]*keys[k][d], bf16 hi/lo ----------------
__global__ void __launch_bounds__(256) k_W1(const float* __restrict__ Wq) {
    __shared__ float keysS[32 * 256];
    __shared__ float aS[8 * 64];
    int t = threadIdx.x;
    int h0 = blockIdx.x * 64;
    int head = blockIdx.y;
#pragma unroll
    for (int i = 0; i < 32; i++) keysS[t + i * 256] = g_keys[t + i * 256];
    float acc[8];
#pragma unroll
    for (int j = 0; j < 8; j++) acc[j] = 0.f;
    int k4 = t >> 6, hl = t & 63;
    for (int dc = 0; dc < 32; dc++) {
        __syncthreads();
#pragma unroll
        for (int i = 0; i < 2; i++) {
            int e = t + i * 256;
            int dd = e >> 6, hh = e & 63;
            aS[dd * 64 + hh] = Wq[(size_t)(head * 256 + dc * 8 + dd) * 2048 + h0 + hh];
        }
        __syncthreads();
#pragma unroll
        for (int dd = 0; dd < 8; dd++) {
            float a = aS[dd * 64 + hl];
            int dg = dc * 8 + dd;
#pragma unroll
            for (int j = 0; j < 8; j++) acc[j] += a * keysS[(k4 * 8 + j) * 256 + dg];
        }
    }
    float scale = g_temp[head] * 0.0625f;
#pragma unroll
    for (int j = 0; j < 8; j++) {
        float v = acc[j] * scale;
        __nv_bfloat16 h, l;
        split_bf16(v, h, l);
        size_t o = (size_t)(head * 32 + k4 * 8 + j) * 2048 + h0 + hl;
        g_W1Thi[o] = h;
        g_W1Tlo[o] = l;
    }
}

// ---------------- 7) W2T[j][nk] = sum_d values[k][d]*Wo[j][n*256+d], bf16 hi/lo ----------------
__global__ void __launch_bounds__(128) k_W2(const float* __restrict__ Wo) {
    __shared__ float woS[1024];
    __shared__ float valT[256 * 33];
    int t = threadIdx.x;
    int j = blockIdx.x;
#pragma unroll
    for (int i = 0; i < 8; i++) woS[t + i * 128] = Wo[(size_t)j * 1024 + t + i * 128];
#pragma unroll
    for (int i = 0; i < 64; i++) {
        int e = t + i * 128;
        int k = e >> 8, d = e & 255;
        valT[d * 33 + k] = g_vals[e];
    }
    __syncthreads();
    int n = t >> 5, k = t & 31;
    float acc = 0.f;
#pragma unroll 8
    for (int d = 0; d < 256; d++) acc += valT[d * 33 + k] * woS[n * 256 + d];
    __nv_bfloat16 h, l;
    split_bf16(acc, h, l);
    g_W2Thi[(size_t)j * 128 + t] = h;
    g_W2Tlo[(size_t)j * 128 + t] = l;
}

// ---------------- 8) GEMM1 (tensor cores) + bias + softmax, writes attn as bf16 hi/lo ----------------
// M-tile 128 x N 128, K=2048 in KC=32 chunks, cp.async double buffer.
__global__ void __launch_bounds__(256) k_gemm1() {
    extern __shared__ __align__(16) __nv_bfloat16 sm1[];
    __nv_bfloat16* sA = sm1;
    __nv_bfloat16* sB = sm1 + 20480;

    int t = threadIdx.x;
    int lane = t & 31, w = t >> 5;
    int wm = w & 3, wn = w >> 2;
    int m0 = blockIdx.x * 128;

    float acc[2][8][4];
#pragma unroll
    for (int mt = 0; mt < 2; mt++)
#pragma unroll
        for (int nt = 0; nt < 8; nt++)
#pragma unroll
            for (int e = 0; e < 4; e++) acc[mt][nt][e] = 0.f;

    int lr = t >> 1;
    int s2 = (t & 1) * 2;

#pragma unroll
    for (int c = 0; c < 2; c++) {
        int kc = c;
#pragma unroll
        for (int p = 0; p < 2; p++) {
            const __nv_bfloat16* gA = p ? g_hid_lo : g_hid_hi;
            const __nv_bfloat16* gB = p ? g_W1Tlo : g_W1Thi;
            __nv_bfloat16* dA = sA + (c * 2 + p) * 5120;
            __nv_bfloat16* dB = sB + (c * 2 + p) * 5120;
#pragma unroll
            for (int s = 0; s < 2; s++) {
                int seg = s2 + s;
                cp16(smem_u32(dA + lr * 40 + seg * 8), gA + (size_t)(m0 + lr) * 2048 + kc * 32 + seg * 8);
                cp16(smem_u32(dB + lr * 40 + seg * 8), gB + (size_t)lr * 2048 + kc * 32 + seg * 8);
            }
        }
        cp_commit();
    }

    int lrow = lane & 15;
    int lk   = (lane >> 4) << 3;

    for (int i = 0; i < 64; i++) {
        if (i < 63) asm volatile("cp.async.wait_group 1;");
        else        asm volatile("cp.async.wait_group 0;");
        __syncthreads();

        int st = i & 1;
        const __nv_bfloat16* Ah = sA + (st * 2 + 0) * 5120;
        const __nv_bfloat16* Al = sA + (st * 2 + 1) * 5120;
        const __nv_bfloat16* Bh = sB + (st * 2 + 0) * 5120;
        const __nv_bfloat16* Bl = sB + (st * 2 + 1) * 5120;

#pragma unroll
        for (int ks = 0; ks < 2; ks++) {
            int ko = ks * 16 + lk;
            unsigned ah[2][4], al[2][4], bb[4][4];
#pragma unroll
            for (int mt = 0; mt < 2; mt++)
                ldsm4(ah[mt], smem_u32(Ah + (wm * 32 + mt * 16 + lrow) * 40 + ko));
#pragma unroll
            for (int mt = 0; mt < 2; mt++)
                ldsm4(al[mt], smem_u32(Al + (wm * 32 + mt * 16 + lrow) * 40 + ko));
#pragma unroll
            for (int g = 0; g < 4; g++)
                ldsm4(bb[g], smem_u32(Bh + (wn * 64 + g * 16 + lrow) * 40 + ko));
#pragma unroll
            for (int mt = 0; mt < 2; mt++)
#pragma unroll
                for (int nt = 0; nt < 8; nt++)
                    mma16816(acc[mt][nt], ah[mt], bb[nt >> 1][nt & 1], bb[nt >> 1][(nt & 1) + 2]);
#pragma unroll
            for (int mt = 0; mt < 2; mt++)
#pragma unroll
                for (int nt = 0; nt < 8; nt++)
                    mma16816(acc[mt][nt], al[mt], bb[nt >> 1][nt & 1], bb[nt >> 1][(nt & 1) + 2]);
#pragma unroll
            for (int g = 0; g < 4; g++)
                ldsm4(bb[g], smem_u32(Bl + (wn * 64 + g * 16 + lrow) * 40 + ko));
#pragma unroll
            for (int mt = 0; mt < 2; mt++)
#pragma unroll
                for (int nt = 0; nt < 8; nt++)
                    mma16816(acc[mt][nt], ah[mt], bb[nt >> 1][nt & 1], bb[nt >> 1][(nt & 1) + 2]);
        }
        __syncthreads();

        if (i + 2 < 64) {
            int kc = i + 2;
#pragma unroll
            for (int p = 0; p < 2; p++) {
                const __nv_bfloat16* gA = p ? g_hid_lo : g_hid_hi;
                const __nv_bfloat16* gB = p ? g_W1Tlo : g_W1Thi;
                __nv_bfloat16* dA = sA + (st * 2 + p) * 5120;
                __nv_bfloat16* dB = sB + (st * 2 + p) * 5120;
#pragma unroll
                for (int s = 0; s < 2; s++) {
                    int seg = s2 + s;
                    cp16(smem_u32(dA + lr * 40 + seg * 8), gA + (size_t)(m0 + lr) * 2048 + kc * 32 + seg * 8);
                    cp16(smem_u32(dB + lr * 40 + seg * 8), gB + (size_t)lr * 2048 + kc * 32 + seg * 8);
                }
            }
            cp_commit();
        }
    }

    // epilogue: bias + per-(row, head) softmax, write bf16 hi/lo attn
    float bias8[4][2];
#pragma unroll
    for (int g = 0; g < 4; g++) {
        bias8[g][0] = g_bias[g * 8 + (lane & 3) * 2];
        bias8[g][1] = g_bias[g * 8 + (lane & 3) * 2 + 1];
    }

#pragma unroll
    for (int mt = 0; mt < 2; mt++) {
#pragma unroll
        for (int h2 = 0; h2 < 2; h2++) {
            int row = m0 + wm * 32 + mt * 16 + (lane >> 2) + h2 * 8;
#pragma unroll
            for (int hd = 0; hd < 2; hd++) {
                float s[8];
#pragma unroll
                for (int g = 0; g < 4; g++) {
                    int nt = hd * 4 + g;
                    s[g * 2]     = acc[mt][nt][h2 * 2]     + bias8[g][0];
                    s[g * 2 + 1] = acc[mt][nt][h2 * 2 + 1] + bias8[g][1];
                }
                float mx = s[0];
#pragma unroll
                for (int e = 1; e < 8; e++) mx = fmaxf(mx, s[e]);
                mx = fmaxf(mx, __shfl_xor_sync(0xffffffffu, mx, 1));
                mx = fmaxf(mx, __shfl_xor_sync(0xffffffffu, mx, 2));
                float ex[8], sum = 0.f;
#pragma unroll
                for (int e = 0; e < 8; e++) { ex[e] = __expf(s[e] - mx); sum += ex[e]; }
                sum += __shfl_xor_sync(0xffffffffu, sum, 1);
                sum += __shfl_xor_sync(0xffffffffu, sum, 2);
                float inv = 1.0f / sum;
#pragma unroll
                for (int g = 0; g < 4; g++) {
                    int col = wn * 64 + hd * 32 + g * 8 + (lane & 3) * 2;
                    float a0 = ex[g * 2] * inv, a1 = ex[g * 2 + 1] * inv;
                    __nv_bfloat16 h0b, l0b, h1b, l1b;
                    split_bf16(a0, h0b, l0b);
                    split_bf16(a1, h1b, l1b);
                    size_t o = (size_t)row * 128 + col;
                    *reinterpret_cast<__nv_bfloat162*>(&g_attn_hi[o]) = __nv_bfloat162(h0b, h1b);
                    *reinterpret_cast<__nv_bfloat162*>(&g_attn_lo[o]) = __nv_bfloat162(l0b, l1b);
                }
            }
        }
    }
}

// ---------------- 9) GEMM2 (tensor cores): out = attn @ W2T^T ----------------
__global__ void __launch_bounds__(256) k_gemm2(float* __restrict__ out) {
    extern __shared__ __align__(16) __nv_bfloat16 sm2[];
    __nv_bfloat16* sA = sm2;
    __nv_bfloat16* sB = sm2 + 2 * 17408;

    int t = threadIdx.x;
    int lane = t & 31, w = t >> 5;
    int wm = w & 3, wn = w >> 2;
    int n0 = blockIdx.x * 128;
    int m0 = blockIdx.y * 128;

    int lr = t >> 1;
    int sg0 = (t & 1) * 8;
#pragma unroll
    for (int p = 0; p < 2; p++) {
        const __nv_bfloat16* gA = p ? g_attn_lo : g_attn_hi;
        const __nv_bfloat16* gB = p ? g_W2Tlo : g_W2Thi;
        __nv_bfloat16* dA = sA + p * 17408;
        __nv_bfloat16* dB = sB + p * 17408;
#pragma unroll
        for (int s = 0; s < 8; s++) {
            int seg = sg0 + s;
            cp16(smem_u32(dA + lr * 136 + seg * 8), gA + (size_t)(m0 + lr) * 128 + seg * 8);
            cp16(smem_u32(dB + lr * 136 + seg * 8), gB + (size_t)(n0 + lr) * 128 + seg * 8);
        }
    }
    cp_commit();
    asm volatile("cp.async.wait_group 0;");
    __syncthreads();

    float acc[2][8][4];
#pragma unroll
    for (int mt = 0; mt < 2; mt++)
#pragma unroll
        for (int nt = 0; nt < 8; nt++)
#pragma unroll
            for (int e = 0; e < 4; e++) acc[mt][nt][e] = 0.f;

    int lrow = lane & 15;
    int lk   = (lane >> 4) << 3;
    const __nv_bfloat16* Ah = sA;
    const __nv_bfloat16* Al = sA + 17408;
    const __nv_bfloat16* Bh = sB;
    const __nv_bfloat16* Bl = sB + 17408;

#pragma unroll
    for (int ks = 0; ks < 8; ks++) {
        int ko = ks * 16 + lk;
        unsigned ah[2][4], al[2][4], bb[4][4];
#pragma unroll
        for (int mt = 0; mt < 2; mt++)
            ldsm4(ah[mt], smem_u32(Ah + (wm * 32 + mt * 16 + lrow) * 136 + ko));
#pragma unroll
        for (int mt = 0; mt < 2; mt++)
            ldsm4(al[mt], smem_u32(Al + (wm * 32 + mt * 16 + lrow) * 136 + ko));
#pragma unroll
        for (int g = 0; g < 4; g++)
            ldsm4(bb[g], smem_u32(Bh + (wn * 64 + g * 16 + lrow) * 136 + ko));
#pragma unroll
        for (int mt = 0; mt < 2; mt++)
#pragma unroll
            for (int nt = 0; nt < 8; nt++)
                mma16816(acc[mt][nt], ah[mt], bb[nt >> 1][nt & 1], bb[nt >> 1][(nt & 1) + 2]);
#pragma unroll
        for (int mt = 0; mt < 2; mt++)
#pragma unroll
            for (int nt = 0; nt < 8; nt++)
                mma16816(acc[mt][nt], al[mt], bb[nt >> 1][nt & 1], bb[nt >> 1][(nt & 1) + 2]);
#pragma unroll
        for (int g = 0; g < 4; g++)
            ldsm4(bb[g], smem_u32(Bl + (wn * 64 + g * 16 + lrow) * 136 + ko));
#pragma unroll
        for (int mt = 0; mt < 2; mt++)
#pragma unroll
            for (int nt = 0; nt < 8; nt++)
                mma16816(acc[mt][nt], ah[mt], bb[nt >> 1][nt & 1], bb[nt >> 1][(nt & 1) + 2]);
    }

#pragma unroll
    for (int mt = 0; mt < 2; mt++) {
        int r0 = m0 + wm * 32 + mt * 16 + (lane >> 2);
#pragma unroll
        for (int nt = 0; nt < 8; nt++) {
            int col = n0 + wn * 64 + nt * 8 + (lane & 3) * 2;
            *reinterpret_cast<float2*>(&out[(size_t)r0 * 2048 + col]) =
                make_float2(acc[mt][nt][0], acc[mt][nt][1]);
            *reinterpret_cast<float2*>(&out[(size_t)(r0 + 8) * 2048 + col]) =
                make_float2(acc[mt][nt][2], acc[mt][nt][3]);
        }
    }
}

// ---------------- launch ----------------
extern "C" void kernel_launch(void* const* d_in, const int* in_sizes, int n_in,
                              void* d_out, int out_size) {
    const float* hidden   = (const float*)d_in[0];
    const float* beliefs  = (const float*)d_in[1];
    const int*   mask     = (const int*)d_in[2];
    const float* goal_emb = (const float*)d_in[3];
    const float* goal_pri = (const float*)d_in[4];
    const float* Wq       = (const float*)d_in[5];
    const float* Wo       = (const float*)d_in[6];
    const float* log_temp = (const float*)d_in[7];
    float* out = (float*)d_out;

    const int SMEM1 = 2 * 2 * 128 * 40 * 2 * 2;      // 81920 B
    const int SMEM2 = 4 * 128 * 136 * 2;             // 139264 B
    static bool attr_done = false;
    if (!attr_done) {
        cudaFuncSetAttribute(k_gemm1, cudaFuncAttributeMaxDynamicSharedMemorySize, SMEM1);
        cudaFuncSetAttribute(k_gemm2, cudaFuncAttributeMaxDynamicSharedMemorySize, SMEM2);
        attr_done = true;
    }

    k_convsum<<<dim3(64, 8), 256>>>(hidden);
    k_mean<<<8, 256>>>();
    k_q1024<<<128, 256>>>(Wq);
    k_rq<<<1, 256>>>();
    k_rough<<<8192, 256>>>(beliefs, mask);
    k_topA<<<256, 256>>>();
    k_topB<<<1, 1024>>>();
    k_prep<<<1, 1024>>>(beliefs, goal_emb, goal_pri, log_temp);
    k_W1<<<dim3(32, 4), 256>>>(Wq);
    k_W2<<<2048, 128>>>(Wo);
    k_gemm1<<<128, 256, SMEM1>>>();
    k_gemm2<<<dim3(16, 128), 256, SMEM2>>>(out);
}